// round 8
// baseline (speedup 1.0000x reference)
#include <cuda_runtime.h>
#include <cuda_bf16.h>

#define NB 16384
#define LL 1024

__device__ double       g_acc   = 0.0;  // 0 at every kernel entry; last block restores
__device__ unsigned int g_count = 0;    // ditto

__global__ __launch_bounds__(256) void bicut_fused(
    const float4* __restrict__ out4,   // output as float4: row stride 512
    const int4*   __restrict__ lab4,   // labels (int32) as int4: row stride 256
    float*        __restrict__ out)
{
    const int row = blockIdx.x;
    const int tid = threadIdx.x;
    const int j0  = tid * 4;

    // ---- load output pairs (positions j0..j0+3) and labels up-front ----
    const float4* orow = out4 + (size_t)row * 512;
    float4 a = orow[tid * 2];       // j0, j0+1 : (o0,o1,o0,o1)
    float4 b = orow[tid * 2 + 1];   // j0+2, j0+3
    int4   l = lab4[(size_t)row * 256 + tid];

    // ---- last index with o1 <= o0 (argmax tie-break: temp=1 iff o1 > o0) ----
    int tz = -1;
    if (a.y <= a.x) tz = j0;
    if (a.w <= a.z) tz = j0 + 1;
    if (b.y <= b.x) tz = j0 + 2;
    if (b.w <= b.z) tz = j0 + 3;

    __shared__ int   smax[8];
    __shared__ float ssum[8];

    int m = __reduce_max_sync(0xffffffffu, tz);
    if ((tid & 31) == 0) smax[tid >> 5] = m;
    __syncthreads();
    if (tid < 32) {
        int v = (tid < 8) ? smax[tid] : -1;
        v = __reduce_max_sync(0xffffffffu, v);
        if (tid == 0) smax[0] = v;
    }
    __syncthreads();
    int idx = smax[0];
    if (idx < 0) idx = LL - 1;   // all-ones row: mask is all ones anyway

    // ---- masked weighted sum ----
    const float INV_ALPHA = 1.0f / 0.65f;
    float o1v[4] = {a.y, a.w, b.y, b.w};
    int   lv[4]  = {l.x, l.y, l.z, l.w};

    float s = 0.0f;
    #pragma unroll
    for (int k = 0; k < 4; k++) {
        int j = j0 + k;
        if (j <= idx) {
            float jf = (float)j;
            float r = (lv[k] == 1) ? (-1.0f / __log2f(jf + 2.0f))
                                   : ((jf + 1.0f) * INV_ALPHA);
            s += o1v[k] * r;
        }
    }

    // ---- block sum ----
    #pragma unroll
    for (int o = 16; o; o >>= 1) s += __shfl_xor_sync(0xffffffffu, s, o);
    if ((tid & 31) == 0) ssum[tid >> 5] = s;
    __syncthreads();

    if (tid == 0) {
        float t = 0.0f;
        #pragma unroll
        for (int w = 0; w < 8; w++) t += ssum[w];

        // relaxed REDG into the global double accumulator (L2 atomic, no fence)
        atomicAdd(&g_acc, (double)t);

        // release-only ticket: orders the REDG above, does NOT invalidate L1
        unsigned int v;
        asm volatile("atom.release.gpu.global.add.u32 %0, [%1], %2;"
                     : "=r"(v) : "l"(&g_count), "r"(1u) : "memory");

        if (v == (unsigned)(NB - 1)) {
            // single acquire in the whole grid: sees all REDGs via the
            // release->acquire chain on g_count's RMW total order
            double acc;
            asm volatile("ld.acquire.gpu.global.f64 %0, [%1];"
                         : "=d"(acc) : "l"(&g_acc) : "memory");
            out[0] = (float)(acc * (1.0 / (double)NB));
            // restore initial state for the next graph replay
            g_acc   = 0.0;
            g_count = 0;
        }
    }
}

extern "C" void kernel_launch(void* const* d_in, const int* in_sizes, int n_in,
                              void* d_out, int out_size) {
    const float4* out4 = (const float4*)d_in[0];
    const int4*   lab4 = (const int4*)d_in[1];
    float* out = (float*)d_out;

    bicut_fused<<<NB, 256>>>(out4, lab4, out);
}